// round 5
// baseline (speedup 1.0000x reference)
#include <cuda_runtime.h>
#include <cuda_bf16.h>
#include <stdint.h>

#define RBOX   500000
#define KCLS   10
#define NSCAL  (RBOX * 11)          // 5,500,000 floats in scores
#define NV4    (NSCAL / 4)          // 1,375,000 float4s (exact)
#define TTOP   2048
#define SCORE_T 0.05f
#define NMS_T   0.5f
#define CLS_OFF 3001.0f
#define IMG_W   1920.0f
#define IMG_H   1080.0f

#define HBASE  125542u              // bits(0.05f) >> 13
#define HBINS  4506
#define CAP    4096
#define ECAP   4096
#define NSUB   42969                // ceil(NV4 / 32) subtiles of 32 float4 (128 floats)

#define GRID   148                  // <= SM count: all blocks co-resident (persistent)
#define TPB    1024
#define GWARPS (GRID * 32)          // 4736 global warps

// ---------------- device scratch ----------------
__device__ unsigned int       g_hist[HBINS];
__device__ unsigned int       g_tilemax[NSUB + 64];
__device__ unsigned int       g_cnt;
__device__ unsigned long long g_keys[CAP];
__device__ float              g_nbox[TTOP * 4];
__device__ float              g_obox[TTOP * 4];
__device__ float              g_oscore[TTOP];
__device__ unsigned int       g_ecnt;
__device__ unsigned int       g_edges[ECAP];
__device__ unsigned int       g_barcnt;
__device__ volatile unsigned  g_bargen;

// -------- software grid barrier (all GRID blocks resident by construction) --------
__device__ __forceinline__ void grid_barrier() {
    __syncthreads();
    if (threadIdx.x == 0) {
        unsigned gen = g_bargen;
        __threadfence();                            // publish my block's writes
        if (atomicAdd(&g_barcnt, 1u) == GRID - 1u) {
            atomicExch(&g_barcnt, 0u);
            __threadfence();
            g_bargen = gen + 1u;                    // release
        } else {
            while (g_bargen == gen) { }             // volatile spin
        }
        __threadfence();
    }
    __syncthreads();
}

__global__ void __launch_bounds__(TPB) k_fused(const float* __restrict__ boxes,
                                               const float* __restrict__ scores,
                                               const float* __restrict__ center,
                                               float* __restrict__ out) {
    __shared__ __align__(16) char sbuf[33 * 1024];
    __shared__ unsigned s_cut;
    const int t = threadIdx.x;
    const int b = blockIdx.x;
    const unsigned lane = (unsigned)t & 31u;
    const unsigned wg   = (unsigned)b * 32u + ((unsigned)t >> 5);   // global warp id

    // ================= P0: zero global state =================
    for (int i = b * TPB + t; i < HBINS; i += GRID * TPB) g_hist[i] = 0u;
    for (int i = b * TPB + t; i < TTOP * 4; i += GRID * TPB) { g_obox[i] = 0.f; g_nbox[i] = 0.f; }
    for (int i = b * TPB + t; i < TTOP; i += GRID * TPB) g_oscore[i] = 0.f;
    if (b == 0 && t == 0) { g_cnt = 0u; g_ecnt = 0u; }
    grid_barrier();

    // ================= P1: histogram + per-subtile max =================
    {
        unsigned* sh = (unsigned*)sbuf;             // 18 KB
        for (int i = t; i < HBINS; i += TPB) sh[i] = 0u;
        __syncthreads();
        const float4* s4 = (const float4*)scores;
        for (unsigned st = wg; st < NSUB; st += GWARPS) {
            unsigned q = st * 32u + lane;
            unsigned maxb = 0u;
            if (q < NV4) {
                float4 v = __ldg(&s4[q]);
                unsigned gi = q * 4u;
                #pragma unroll
                for (int e = 0; e < 4; e++) {
                    float val = (e == 0) ? v.x : (e == 1) ? v.y : (e == 2) ? v.z : v.w;
                    unsigned g = gi + e;
                    unsigned r = g / 11u;
                    unsigned c = g - r * 11u;
                    if (c != 0u) {
                        float fg = val * center[r];
                        if (fg > SCORE_T) {
                            unsigned bits = __float_as_uint(fg);
                            unsigned bin = (bits >> 13) - HBASE;
                            if (bin >= HBINS) bin = HBINS - 1;
                            atomicAdd(&sh[bin], 1u);
                            if (bits > maxb) maxb = bits;
                        }
                    }
                }
            }
            #pragma unroll
            for (int off = 16; off > 0; off >>= 1)
                maxb = max(maxb, __shfl_xor_sync(0xFFFFFFFFu, maxb, off));
            if (lane == 0u) g_tilemax[st] = maxb;
        }
        __syncthreads();
        for (int i = t; i < HBINS; i += TPB) {
            unsigned v = sh[i];
            if (v) atomicAdd(&g_hist[i], v);
        }
    }
    grid_barrier();

    // ================= P2: replicated suffix-scan -> cut bin (per block) =================
    {
        unsigned* part  = (unsigned*)sbuf;          // 4 KB
        unsigned* sincl = part + 1024;              // 4 KB
        if (t == 0) s_cut = 0u;
        const int CH = 5;
        int lo = t * CH;
        int hi = lo + CH; if (hi > HBINS) hi = HBINS; if (lo > HBINS) lo = HBINS;
        unsigned loc[5];
        unsigned p = 0u;
        for (int bin = lo; bin < hi; bin++) { loc[bin - lo] = __ldcg(&g_hist[bin]); p += loc[bin - lo]; }
        part[t] = p; sincl[t] = p;
        __syncthreads();
        for (int off = 1; off < 1024; off <<= 1) {
            unsigned v = (t + off < 1024) ? sincl[t + off] : 0u;
            __syncthreads();
            sincl[t] += v;
            __syncthreads();
        }
        unsigned total = sincl[0];
        if (total >= TTOP) {
            unsigned above = sincl[t] - part[t];
            if (above < TTOP && sincl[t] >= TTOP) {
                unsigned run = above;
                for (int bin = hi - 1; bin >= lo; bin--) {
                    run += loc[bin - lo];
                    if (run >= TTOP) { s_cut = (unsigned)bin; break; }
                }
            }
        }
        __syncthreads();
    }
    const unsigned cut = s_cut;

    // ================= P3: compact (warp-per-subtile with tilemax skip) =================
    {
        const float4* s4 = (const float4*)scores;
        for (unsigned st = wg; st < NSUB; st += GWARPS) {
            if ((g_tilemax[st] >> 13) < HBASE + cut) continue;   // same warp wrote it
            unsigned q = st * 32u + lane;
            if (q >= NV4) continue;
            float4 v = __ldg(&s4[q]);
            unsigned gi = q * 4u;
            #pragma unroll
            for (int e = 0; e < 4; e++) {
                float val = (e == 0) ? v.x : (e == 1) ? v.y : (e == 2) ? v.z : v.w;
                unsigned g = gi + e;
                unsigned r = g / 11u;
                unsigned c = g - r * 11u;
                if (c != 0u) {
                    float fg = val * center[r];
                    if (fg > SCORE_T) {
                        unsigned bits = __float_as_uint(fg);
                        if ((bits >> 13) >= HBASE + cut) {
                            unsigned j = r * 10u + (c - 1u);
                            unsigned pos = atomicAdd(&g_cnt, 1u);
                            if (pos < CAP) {
                                g_keys[pos] = ((unsigned long long)bits << 32) |
                                              (unsigned long long)(0xFFFFFFFFu - j);
                            }
                        }
                    }
                }
            }
        }
    }
    grid_barrier();

    // ================= P4: rank-by-count + gather + scatter =================
    {
        unsigned n = __ldcg(&g_cnt); if (n > CAP) n = CAP;
        unsigned long long* sk = (unsigned long long*)sbuf;      // up to 32 KB
        for (unsigned i = t; i < n; i += TPB) sk[i] = __ldcg(&g_keys[i]);
        __syncthreads();
        for (unsigned cand = wg; cand < n; cand += GWARPS) {
            unsigned long long mykey = sk[cand];
            unsigned cnt = 0u;
            for (unsigned j = lane; j < n; j += 32u)
                cnt += (sk[j] > mykey) ? 1u : 0u;
            #pragma unroll
            for (int off = 16; off > 0; off >>= 1)
                cnt += __shfl_xor_sync(0xFFFFFFFFu, cnt, off);
            if (lane == 0u && cnt < TTOP) {
                unsigned rank = cnt;
                unsigned j = 0xFFFFFFFFu - (unsigned)(mykey & 0xFFFFFFFFull);
                float s = __uint_as_float((unsigned)(mykey >> 32));
                unsigned r = j / 10u;
                unsigned cls = j - r * 10u;
                float x1 = boxes[r * 4 + 0], y1 = boxes[r * 4 + 1];
                float x2 = boxes[r * 4 + 2], y2 = boxes[r * 4 + 3];
                float b0 = fminf(fmaxf(x1, 0.f), IMG_W);
                float b1 = fminf(fmaxf(y1, 0.f), IMG_H);
                float b2 = fminf(fmaxf(x2, 0.f), IMG_W);
                float b3 = fminf(fmaxf(y2, 0.f), IMG_H);
                float off2 = (float)cls * CLS_OFF;
                g_obox[rank * 4 + 0] = b0; g_obox[rank * 4 + 1] = b1;
                g_obox[rank * 4 + 2] = b2; g_obox[rank * 4 + 3] = b3;
                g_nbox[rank * 4 + 0] = b0 + off2; g_nbox[rank * 4 + 1] = b1 + off2;
                g_nbox[rank * 4 + 2] = b2 + off2; g_nbox[rank * 4 + 3] = b3 + off2;
                g_oscore[rank] = s;
            }
        }
    }
    grid_barrier();

    // ================= P5: pairwise IoU -> sparse suppression edges =================
    {
        // 64x64 tiles over the 2048x2048 upper triangle; blocks grid-stride tiles
        for (unsigned tt = (unsigned)b; tt < 1024u; tt += GRID) {
            unsigned bi = tt >> 5, bj = tt & 31u;
            if (bj < bi) continue;
            int i = (int)(bi * 64u) + (t >> 4);          // 64 rows x 16 col-threads
            float ax1 = __ldcg(&g_nbox[i * 4 + 0]), ay1 = __ldcg(&g_nbox[i * 4 + 1]);
            float ax2 = __ldcg(&g_nbox[i * 4 + 2]), ay2 = __ldcg(&g_nbox[i * 4 + 3]);
            float aarea = fmaxf(ax2 - ax1, 0.f) * fmaxf(ay2 - ay1, 0.f);
            #pragma unroll
            for (int k = 0; k < 4; k++) {
                int j = (int)(bj * 64u) + (t & 15) + 16 * k;
                if (j <= i) continue;
                float bx1 = __ldcg(&g_nbox[j * 4 + 0]), by1 = __ldcg(&g_nbox[j * 4 + 1]);
                float bx2 = __ldcg(&g_nbox[j * 4 + 2]), by2 = __ldcg(&g_nbox[j * 4 + 3]);
                float barea = fmaxf(bx2 - bx1, 0.f) * fmaxf(by2 - by1, 0.f);
                float w = fmaxf(fminf(ax2, bx2) - fmaxf(ax1, bx1), 0.f);
                float h = fmaxf(fminf(ay2, by2) - fmaxf(ay1, by1), 0.f);
                float inter = w * h;
                float iou = inter / (aarea + barea - inter + 1e-9f);
                if (iou > NMS_T) {
                    unsigned pos = atomicAdd(&g_ecnt, 1u);
                    if (pos < ECAP) g_edges[pos] = ((unsigned)i << 16) | (unsigned)j;
                }
            }
        }
    }
    grid_barrier();

    // ================= P6: block 0 — sort edges, greedy replay, write output =================
    if (b != 0) return;
    {
        unsigned* se = (unsigned*)sbuf;                       // 16 KB
        unsigned char* keep = (unsigned char*)(sbuf + ECAP * 4); // 2 KB
        unsigned E = __ldcg(&g_ecnt); if (E > ECAP) E = ECAP;
        for (int i = t; i < ECAP; i += TPB) se[i] = (i < (int)E) ? __ldcg(&g_edges[i]) : 0xFFFFFFFFu;
        for (int i = t; i < TTOP; i += TPB) keep[i] = (__ldcg(&g_oscore[i]) > SCORE_T) ? 1 : 0;
        __syncthreads();

        if (E > 1) {
            unsigned P = 2;
            while (P < E) P <<= 1;
            for (unsigned k = 2; k <= P; k <<= 1) {
                for (unsigned jj = k >> 1; jj > 0; jj >>= 1) {
                    for (unsigned i = t; i < P; i += TPB) {
                        unsigned ixj = i ^ jj;
                        if (ixj > i) {
                            bool up = ((i & k) == 0);
                            unsigned a = se[i], bb = se[ixj];
                            bool sw = up ? (a > bb) : (a < bb);
                            if (sw) { se[i] = bb; se[ixj] = a; }
                        }
                    }
                    __syncthreads();
                }
            }
        }
        if (t == 0) {
            for (unsigned e = 0; e < E; e++) {
                unsigned v = se[e];
                unsigned i = v >> 16, j = v & 0xFFFFu;
                if (keep[i]) keep[j] = 0;
            }
        }
        __syncthreads();
        for (int i = t; i < TTOP; i += TPB) {
            bool kp = keep[i] != 0;
            out[i * 5 + 0] = kp ? __ldcg(&g_obox[i * 4 + 0]) : 0.f;
            out[i * 5 + 1] = kp ? __ldcg(&g_obox[i * 4 + 1]) : 0.f;
            out[i * 5 + 2] = kp ? __ldcg(&g_obox[i * 4 + 2]) : 0.f;
            out[i * 5 + 3] = kp ? __ldcg(&g_obox[i * 4 + 3]) : 0.f;
            out[i * 5 + 4] = kp ? __ldcg(&g_oscore[i]) : 0.f;
        }
    }
}

// ---------------- launch ----------------
extern "C" void kernel_launch(void* const* d_in, const int* in_sizes, int n_in,
                              void* d_out, int out_size) {
    const float* boxes  = nullptr;
    const float* scores = nullptr;
    const float* center = nullptr;
    for (int i = 0; i < n_in; i++) {
        if (in_sizes[i] == RBOX * 4)       boxes  = (const float*)d_in[i];
        else if (in_sizes[i] == RBOX * 11) scores = (const float*)d_in[i];
        else if (in_sizes[i] == RBOX)      center = (const float*)d_in[i];
    }
    if (!boxes)  boxes  = (const float*)d_in[0];
    if (!scores) scores = (const float*)d_in[1];
    if (!center) center = (const float*)d_in[2];
    float* out = (float*)d_out;

    k_fused<<<GRID, TPB>>>(boxes, scores, center, out);
}

// round 6
// speedup vs baseline: 1.0254x; 1.0254x over previous
#include <cuda_runtime.h>
#include <cuda_bf16.h>
#include <stdint.h>

#define RBOX   500000
#define KCLS   10
#define NSCAL  (RBOX * 11)          // 5,500,000 floats in scores
#define NV4    (NSCAL / 4)          // 1,375,000 float4s (exact)
#define TTOP   2048
#define SCORE_T 0.05f
#define NMS_T   0.5f
#define CLS_OFF 3001.0f
#define IMG_W   1920.0f
#define IMG_H   1080.0f

#define HBASE  125542u              // bits(0.05f) >> 13
#define HBINS  4506
#define CAP    4096
#define ECAP   4096
#define NSUB   42969                // ceil(NV4 / 32) subtiles of 32 float4 (128 floats)

#define GRID   296                  // 2 CTAs/SM, all co-resident (persistent)
#define TPB    1024
#define GWARPS (GRID * 32)          // 9472 global warps

// ---------------- device scratch ----------------
__device__ unsigned int       g_hist[HBINS];
__device__ unsigned int       g_tilemax[NSUB + 64];
__device__ unsigned int       g_cnt;
__device__ unsigned long long g_keys[CAP];
__device__ float              g_nbox[TTOP * 4];
__device__ float              g_obox[TTOP * 4];
__device__ float              g_oscore[TTOP];
__device__ unsigned int       g_ecnt;
__device__ unsigned int       g_edges[ECAP];
__device__ unsigned int       g_barcnt;
__device__ volatile unsigned  g_bargen;

// -------- software grid barrier (all GRID blocks resident by construction) --------
__device__ __forceinline__ void grid_barrier() {
    __syncthreads();
    if (threadIdx.x == 0) {
        unsigned gen = g_bargen;
        __threadfence();
        if (atomicAdd(&g_barcnt, 1u) == GRID - 1u) {
            atomicExch(&g_barcnt, 0u);
            __threadfence();
            g_bargen = gen + 1u;
        } else {
            while (g_bargen == gen) { }
        }
        __threadfence();
    }
    __syncthreads();
}

__global__ void __launch_bounds__(TPB, 2) k_fused(const float* __restrict__ boxes,
                                                  const float* __restrict__ scores,
                                                  const float* __restrict__ center,
                                                  float* __restrict__ out) {
    __shared__ __align__(16) char sbuf[33 * 1024];
    __shared__ unsigned s_cut;
    const int t = threadIdx.x;
    const int b = blockIdx.x;
    const unsigned lane = (unsigned)t & 31u;
    const unsigned wg   = (unsigned)b * 32u + ((unsigned)t >> 5);   // global warp id

    // ================= P0: zero hist + counters =================
    for (int i = b * TPB + t; i < HBINS; i += GRID * TPB) g_hist[i] = 0u;
    if (b == 0 && t == 0) { g_cnt = 0u; g_ecnt = 0u; }
    grid_barrier();

    // ================= P1: histogram + per-subtile max =================
    {
        unsigned* sh = (unsigned*)sbuf;             // 18 KB
        for (int i = t; i < HBINS; i += TPB) sh[i] = 0u;
        __syncthreads();
        const float4* s4 = (const float4*)scores;
        for (unsigned st = wg; st < NSUB; st += GWARPS) {
            unsigned q = st * 32u + lane;
            unsigned maxb = 0u;
            if (q < NV4) {
                float4 v = __ldg(&s4[q]);
                unsigned gi = q * 4u;
                #pragma unroll
                for (int e = 0; e < 4; e++) {
                    float val = (e == 0) ? v.x : (e == 1) ? v.y : (e == 2) ? v.z : v.w;
                    unsigned g = gi + e;
                    unsigned r = g / 11u;
                    unsigned c = g - r * 11u;
                    if (c != 0u) {
                        float fg = val * center[r];
                        if (fg > SCORE_T) {
                            unsigned bits = __float_as_uint(fg);
                            unsigned bin = (bits >> 13) - HBASE;
                            if (bin >= HBINS) bin = HBINS - 1;
                            atomicAdd(&sh[bin], 1u);
                            if (bits > maxb) maxb = bits;
                        }
                    }
                }
            }
            #pragma unroll
            for (int off = 16; off > 0; off >>= 1)
                maxb = max(maxb, __shfl_xor_sync(0xFFFFFFFFu, maxb, off));
            if (lane == 0u) g_tilemax[st] = maxb;
        }
        __syncthreads();
        for (int i = t; i < HBINS; i += TPB) {
            unsigned v = sh[i];
            if (v) atomicAdd(&g_hist[i], v);
        }
    }
    grid_barrier();

    // ================= P2: replicated suffix-scan -> cut bin (per block) =================
    {
        unsigned* part  = (unsigned*)sbuf;
        unsigned* sincl = part + 1024;
        if (t == 0) s_cut = 0u;
        const int CH = 5;
        int lo = t * CH;
        int hi = lo + CH; if (hi > HBINS) hi = HBINS; if (lo > HBINS) lo = HBINS;
        unsigned loc[5];
        unsigned p = 0u;
        for (int bin = lo; bin < hi; bin++) { loc[bin - lo] = __ldcg(&g_hist[bin]); p += loc[bin - lo]; }
        part[t] = p; sincl[t] = p;
        __syncthreads();
        for (int off = 1; off < 1024; off <<= 1) {
            unsigned v = (t + off < 1024) ? sincl[t + off] : 0u;
            __syncthreads();
            sincl[t] += v;
            __syncthreads();
        }
        unsigned total = sincl[0];
        if (total >= TTOP) {
            unsigned above = sincl[t] - part[t];
            if (above < TTOP && sincl[t] >= TTOP) {
                unsigned run = above;
                for (int bin = hi - 1; bin >= lo; bin--) {
                    run += loc[bin - lo];
                    if (run >= TTOP) { s_cut = (unsigned)bin; break; }
                }
            }
        }
        __syncthreads();
    }
    const unsigned cut = s_cut;

    // ================= P3: compact (warp-per-subtile with tilemax skip) =================
    {
        const float4* s4 = (const float4*)scores;
        for (unsigned st = wg; st < NSUB; st += GWARPS) {
            if ((__ldcg(&g_tilemax[st]) >> 13) < HBASE + cut) continue;
            unsigned q = st * 32u + lane;
            if (q >= NV4) continue;
            float4 v = __ldg(&s4[q]);
            unsigned gi = q * 4u;
            #pragma unroll
            for (int e = 0; e < 4; e++) {
                float val = (e == 0) ? v.x : (e == 1) ? v.y : (e == 2) ? v.z : v.w;
                unsigned g = gi + e;
                unsigned r = g / 11u;
                unsigned c = g - r * 11u;
                if (c != 0u) {
                    float fg = val * center[r];
                    if (fg > SCORE_T) {
                        unsigned bits = __float_as_uint(fg);
                        if ((bits >> 13) >= HBASE + cut) {
                            unsigned j = r * 10u + (c - 1u);
                            unsigned pos = atomicAdd(&g_cnt, 1u);
                            if (pos < CAP) {
                                g_keys[pos] = ((unsigned long long)bits << 32) |
                                              (unsigned long long)(0xFFFFFFFFu - j);
                            }
                        }
                    }
                }
            }
        }
    }
    grid_barrier();

    // ================= P4: rank-by-count + gather + scatter =================
    {
        unsigned n = __ldcg(&g_cnt); if (n > CAP) n = CAP;
        unsigned long long* sk = (unsigned long long*)sbuf;      // up to 32 KB
        for (unsigned i = t; i < n; i += TPB) sk[i] = __ldcg(&g_keys[i]);
        __syncthreads();
        for (unsigned cand = wg; cand < n; cand += GWARPS) {
            unsigned long long mykey = sk[cand];
            unsigned cnt = 0u;
            for (unsigned j = lane; j < n; j += 32u)
                cnt += (sk[j] > mykey) ? 1u : 0u;
            #pragma unroll
            for (int off = 16; off > 0; off >>= 1)
                cnt += __shfl_xor_sync(0xFFFFFFFFu, cnt, off);
            if (lane == 0u && cnt < TTOP) {
                unsigned rank = cnt;
                unsigned j = 0xFFFFFFFFu - (unsigned)(mykey & 0xFFFFFFFFull);
                float s = __uint_as_float((unsigned)(mykey >> 32));
                unsigned r = j / 10u;
                unsigned cls = j - r * 10u;
                float x1 = boxes[r * 4 + 0], y1 = boxes[r * 4 + 1];
                float x2 = boxes[r * 4 + 2], y2 = boxes[r * 4 + 3];
                float b0 = fminf(fmaxf(x1, 0.f), IMG_W);
                float b1 = fminf(fmaxf(y1, 0.f), IMG_H);
                float b2 = fminf(fmaxf(x2, 0.f), IMG_W);
                float b3 = fminf(fmaxf(y2, 0.f), IMG_H);
                float off2 = (float)cls * CLS_OFF;
                g_obox[rank * 4 + 0] = b0; g_obox[rank * 4 + 1] = b1;
                g_obox[rank * 4 + 2] = b2; g_obox[rank * 4 + 3] = b3;
                g_nbox[rank * 4 + 0] = b0 + off2; g_nbox[rank * 4 + 1] = b1 + off2;
                g_nbox[rank * 4 + 2] = b2 + off2; g_nbox[rank * 4 + 3] = b3 + off2;
                g_oscore[rank] = s;
            }
        }
    }
    grid_barrier();

    // ================= P5: pairwise IoU -> sparse suppression edges =================
    {
        for (unsigned tt = (unsigned)b; tt < 1024u; tt += GRID) {
            unsigned bi = tt >> 5, bj = tt & 31u;
            if (bj < bi) continue;
            int i = (int)(bi * 64u) + (t >> 4);          // 64 rows x 16 col-threads
            float ax1 = __ldcg(&g_nbox[i * 4 + 0]), ay1 = __ldcg(&g_nbox[i * 4 + 1]);
            float ax2 = __ldcg(&g_nbox[i * 4 + 2]), ay2 = __ldcg(&g_nbox[i * 4 + 3]);
            float aarea = fmaxf(ax2 - ax1, 0.f) * fmaxf(ay2 - ay1, 0.f);
            #pragma unroll
            for (int k = 0; k < 4; k++) {
                int j = (int)(bj * 64u) + (t & 15) + 16 * k;
                if (j <= i) continue;
                float bx1 = __ldcg(&g_nbox[j * 4 + 0]), by1 = __ldcg(&g_nbox[j * 4 + 1]);
                float bx2 = __ldcg(&g_nbox[j * 4 + 2]), by2 = __ldcg(&g_nbox[j * 4 + 3]);
                float barea = fmaxf(bx2 - bx1, 0.f) * fmaxf(by2 - by1, 0.f);
                float w = fmaxf(fminf(ax2, bx2) - fmaxf(ax1, bx1), 0.f);
                float h = fmaxf(fminf(ay2, by2) - fmaxf(ay1, by1), 0.f);
                float inter = w * h;
                float iou = inter / (aarea + barea - inter + 1e-9f);
                if (iou > NMS_T) {
                    unsigned pos = atomicAdd(&g_ecnt, 1u);
                    if (pos < ECAP) g_edges[pos] = ((unsigned)i << 16) | (unsigned)j;
                }
            }
        }
    }
    grid_barrier();

    // ================= P6: block 0 — Jacobi fixpoint NMS + output =================
    if (b != 0) return;
    {
        unsigned* se = (unsigned*)sbuf;                           // 16 KB
        unsigned char* valid = (unsigned char*)(sbuf + ECAP * 4); // 2 KB
        unsigned char* ka = valid + TTOP;                         // 2 KB
        unsigned char* kb = ka + TTOP;                            // 2 KB
        __shared__ int s_changed;
        unsigned n = __ldcg(&g_cnt); if (n > CAP) n = CAP;
        unsigned E = __ldcg(&g_ecnt); if (E > ECAP) E = ECAP;
        for (unsigned i = t; i < E; i += TPB) se[i] = __ldcg(&g_edges[i]);
        for (unsigned i = t; i < TTOP; i += TPB) {
            unsigned char v = (i < n && __ldcg(&g_oscore[i]) > SCORE_T) ? 1 : 0;
            valid[i] = v; ka[i] = v;
        }
        __syncthreads();
        // keep[j] = valid[j] && !exists edge (i<j) with keep[i]; Jacobi to fixpoint
        for (int round = 0; round < TTOP; round++) {
            if (t == 0) s_changed = 0;
            for (unsigned i = t; i < TTOP; i += TPB) kb[i] = valid[i];
            __syncthreads();
            for (unsigned e = t; e < E; e += TPB) {
                unsigned v = se[e];
                unsigned i = v >> 16, j = v & 0xFFFFu;
                if (ka[i]) kb[j] = 0;
            }
            __syncthreads();
            int ch = 0;
            for (unsigned i = t; i < TTOP; i += TPB) {
                if (kb[i] != ka[i]) ch = 1;
                ka[i] = kb[i];
            }
            if (ch) s_changed = 1;
            __syncthreads();
            if (!s_changed) break;
        }
        for (unsigned i = t; i < TTOP; i += TPB) {
            bool kp = ka[i] != 0;
            out[i * 5 + 0] = kp ? __ldcg(&g_obox[i * 4 + 0]) : 0.f;
            out[i * 5 + 1] = kp ? __ldcg(&g_obox[i * 4 + 1]) : 0.f;
            out[i * 5 + 2] = kp ? __ldcg(&g_obox[i * 4 + 2]) : 0.f;
            out[i * 5 + 3] = kp ? __ldcg(&g_obox[i * 4 + 3]) : 0.f;
            out[i * 5 + 4] = kp ? __ldcg(&g_oscore[i]) : 0.f;
        }
    }
}

// ---------------- launch ----------------
extern "C" void kernel_launch(void* const* d_in, const int* in_sizes, int n_in,
                              void* d_out, int out_size) {
    const float* boxes  = nullptr;
    const float* scores = nullptr;
    const float* center = nullptr;
    for (int i = 0; i < n_in; i++) {
        if (in_sizes[i] == RBOX * 4)       boxes  = (const float*)d_in[i];
        else if (in_sizes[i] == RBOX * 11) scores = (const float*)d_in[i];
        else if (in_sizes[i] == RBOX)      center = (const float*)d_in[i];
    }
    if (!boxes)  boxes  = (const float*)d_in[0];
    if (!scores) scores = (const float*)d_in[1];
    if (!center) center = (const float*)d_in[2];
    float* out = (float*)d_out;

    k_fused<<<GRID, TPB>>>(boxes, scores, center, out);
}